// round 3
// baseline (speedup 1.0000x reference)
#include <cuda_runtime.h>
#include <math.h>
#include <stdint.h>

// Problem constants
#define NND   65536      // N nodes
#define DD    256        // feature dim
#define NSS   512        // edge slots
#define EPS_LN   1e-5f
#define EPS_ATTN 1e-8f

// Output layout: [x_out (N*D)] [H (N*NS)] [dots2 (N*NS)]
#define OFF_H   ((size_t)NND * DD)
#define OFF_D2  (OFF_H + (size_t)NND * NSS)

// ------------------------- device scratch (no allocations allowed) -------
__device__ float g_xin[(size_t)NND * DD];          // 64 MB  LN(x)
__device__ float g_qkv[(size_t)NND * 3 * DD];      // 192 MB [q2 | kk | vv] row stride 768
__device__ float g_dots[(size_t)NSS * NND];        // 128 MB edge->node logits
__device__ float g_eln[NSS * DD];
__device__ float g_qe[NSS * DD];
__device__ float g_e2cat[NSS * 2 * DD];            // [e_ln | updates]
__device__ float g_hmlp[NSS * DD];
__device__ float g_enew[NSS * DD];
__device__ float g_k2[NSS * DD];
__device__ float g_eout[NSS * DD];
__device__ float g_wcatT[3 * DD * DD];             // [768][256]: row j = column j of (Wq|Wk|Wv)
__device__ float g_bcat[3 * DD];

// ------------------------- small helpers ---------------------------------
__device__ __forceinline__ unsigned fkey(float f) {
    unsigned u = __float_as_uint(f);
    return (u & 0x80000000u) ? ~u : (u | 0x80000000u); // order-preserving map
}

// ------------------------- weight prep -----------------------------------
__global__ void prep_wcat(const float* __restrict__ Wq, const float* __restrict__ bq,
                          const float* __restrict__ Wk, const float* __restrict__ bk,
                          const float* __restrict__ Wv, const float* __restrict__ bv) {
    int idx = blockIdx.x * 256 + threadIdx.x;     // 768*256 total
    int j = idx >> 8, k = idx & 255;
    const float* W = (j < 256) ? Wq : ((j < 512) ? Wk : Wv);
    int jj = j & 255;
    g_wcatT[idx] = W[k * 256 + jj];
    if (k == 0) {
        const float* bb = (j < 256) ? bq : ((j < 512) ? bk : bv);
        g_bcat[j] = bb[jj];
    }
}

// ------------------------- row LayerNorm (nodes) --------------------------
__global__ void node_ln(const float* __restrict__ x, const float* __restrict__ g,
                        const float* __restrict__ b) {
    int row = blockIdx.x, t = threadIdx.x;   // 256 threads
    __shared__ float red[256];
    float v = x[(size_t)row * DD + t];
    red[t] = v; __syncthreads();
    for (int s = 128; s > 0; s >>= 1) { if (t < s) red[t] += red[t + s]; __syncthreads(); }
    float mean = red[0] * (1.0f / DD);
    __syncthreads();
    float d = v - mean;
    red[t] = d * d; __syncthreads();
    for (int s = 128; s > 0; s >>= 1) { if (t < s) red[t] += red[t + s]; __syncthreads(); }
    float var = red[0] * (1.0f / DD);
    g_xin[(size_t)row * DD + t] = d * rsqrtf(var + EPS_LN) * g[t] + b[t];
}

// ------------------------- edge prep: sample + LN -------------------------
__global__ void edge_prep(const float* __restrict__ noise, const float* __restrict__ mu,
                          const float* __restrict__ ls, const float* __restrict__ g,
                          const float* __restrict__ b) {
    int row = blockIdx.x, t = threadIdx.x;   // 512 blocks x 256 threads
    __shared__ float red[256];
    float v = mu[t] + expf(ls[t]) * noise[row * DD + t];
    red[t] = v; __syncthreads();
    for (int s = 128; s > 0; s >>= 1) { if (t < s) red[t] += red[t + s]; __syncthreads(); }
    float mean = red[0] * (1.0f / DD);
    __syncthreads();
    float d = v - mean;
    red[t] = d * d; __syncthreads();
    for (int s = 128; s > 0; s >>= 1) { if (t < s) red[t] += red[t + s]; __syncthreads(); }
    float var = red[0] * (1.0f / DD);
    float o = d * rsqrtf(var + EPS_LN) * g[t] + b[t];
    g_eln[row * DD + t] = o;
    g_e2cat[row * 2 * DD + t] = o;
}

// ------------- small dense: one row per block, 256 output cols ------------
__global__ void rowgemm(const float* __restrict__ X, int ldx, int K,
                        const float* __restrict__ Wm, const float* __restrict__ bias,
                        float* __restrict__ Y, int ldy, int relu) {
    __shared__ float xr[512];
    int row = blockIdx.x, t = threadIdx.x;
    for (int i = t; i < K; i += 256) xr[i] = X[(size_t)row * ldx + i];
    __syncthreads();
    float acc = bias[t];
    for (int k = 0; k < K; k++) acc = fmaf(xr[k], Wm[k * 256 + t], acc);
    if (relu) acc = fmaxf(acc, 0.0f);
    Y[(size_t)row * ldy + t] = acc;
}

// ------------------------- big SGEMM: C = scale*A*B^T (+bias, relu) -------
// A[M,K] lda, B[N,K] ldb (both K-contiguous), C[M,N] ldc. 128x128x8 tile,
// 256 threads, 8x8 micro. All dims divisible by 128, K by 8.
__global__ void __launch_bounds__(256) sgemm_nt(
        const float* __restrict__ A, int lda,
        const float* __restrict__ B, int ldb,
        float* __restrict__ C, int ldc, int K,
        const float* __restrict__ bias, float scale, int relu_from) {
    __shared__ float As[8][128];
    __shared__ float Bs[8][128];
    int tid = threadIdx.x;
    int bm = blockIdx.y * 128, bn = blockIdx.x * 128;
    int tx = tid & 15, ty = tid >> 4;
    float acc[8][8] = {};
    int lrow = tid >> 1, lk = (tid & 1) * 4;
    const float* Ag = A + (size_t)(bm + lrow) * lda + lk;
    const float* Bg = B + (size_t)(bn + lrow) * ldb + lk;
    for (int k0 = 0; k0 < K; k0 += 8) {
        float4 av = *(const float4*)(Ag + k0);
        float4 bv = *(const float4*)(Bg + k0);
        __syncthreads();
        As[lk + 0][lrow] = av.x; As[lk + 1][lrow] = av.y;
        As[lk + 2][lrow] = av.z; As[lk + 3][lrow] = av.w;
        Bs[lk + 0][lrow] = bv.x; Bs[lk + 1][lrow] = bv.y;
        Bs[lk + 2][lrow] = bv.z; Bs[lk + 3][lrow] = bv.w;
        __syncthreads();
#pragma unroll
        for (int kk = 0; kk < 8; kk++) {
            float a[8], b[8];
#pragma unroll
            for (int i = 0; i < 8; i++) a[i] = As[kk][ty * 8 + i];
#pragma unroll
            for (int j = 0; j < 8; j++) b[j] = Bs[kk][tx * 8 + j];
#pragma unroll
            for (int i = 0; i < 8; i++)
#pragma unroll
                for (int j = 0; j < 8; j++) acc[i][j] = fmaf(a[i], b[j], acc[i][j]);
        }
    }
#pragma unroll
    for (int i = 0; i < 8; i++) {
        int row = bm + ty * 8 + i;
#pragma unroll
        for (int j = 0; j < 8; j++) {
            int col = bn + tx * 8 + j;
            float v = acc[i][j] * scale;
            if (bias) v += bias[col];
            if (col >= relu_from) v = fmaxf(v, 0.0f);
            C[(size_t)row * ldc + col] = v;
        }
    }
}

// ----- edge-side: softmax stats + exact top-k_n select + weighted gather ---
__global__ void __launch_bounds__(1024) edge_select(const int* __restrict__ kn_ptr) {
    const int row = blockIdx.x;
    const int t = threadIdx.x;                    // 1024 threads
    const float* dr = g_dots + (size_t)row * NND;
    __shared__ float red[1024];

    // online max / sum-exp
    float m = -3.0e38f, s = 0.0f;
    for (int i = t; i < NND; i += 1024) {
        float dv = dr[i];
        if (dv > m) { s = s * expf(m - dv) + 1.0f; m = dv; }
        else        { s += expf(dv - m); }
    }
    red[t] = m; __syncthreads();
    for (int st = 512; st > 0; st >>= 1) { if (t < st) red[t] = fmaxf(red[t], red[t + st]); __syncthreads(); }
    float M = red[0]; __syncthreads();
    red[t] = s * expf(m - M); __syncthreads();
    for (int st = 512; st > 0; st >>= 1) { if (t < st) red[t] += red[t + st]; __syncthreads(); }
    float Z = red[0]; __syncthreads();

    // exact radix select of the k-th largest (3 passes: 11+11+10 bits)
    __shared__ unsigned hist[2048];
    __shared__ unsigned sb_bin;
    __shared__ int sb_rem;
    int kq = *kn_ptr;
    unsigned pref = 0, pmask = 0;
    int rem = kq;
    const int shifts[3] = {21, 10, 0};
    const int bcnts[3]  = {2048, 2048, 1024};
    for (int p = 0; p < 3; p++) {
        int bc = bcnts[p], sh = shifts[p];
        for (int i = t; i < bc; i += 1024) hist[i] = 0;
        __syncthreads();
        for (int i = t; i < NND; i += 1024) {
            unsigned key = fkey(dr[i]);
            if ((key & pmask) == pref) atomicAdd(&hist[(key >> sh) & (bc - 1)], 1u);
        }
        __syncthreads();
        if (t == 0) {
            int cum = 0, b = bc - 1;
            for (; b >= 0; b--) { cum += (int)hist[b]; if (cum >= rem) break; }
            if (b < 0) b = 0;
            sb_bin = (unsigned)b;
            sb_rem = rem - (cum - (int)hist[b]);  // how many needed inside this bin
        }
        __syncthreads();
        pref |= sb_bin << sh;
        pmask |= (unsigned)(bc - 1) << sh;
        rem = sb_rem;
        __syncthreads();
    }
    // threshold key == pref; take all keys > pref, plus `rem` keys == pref
    __shared__ int cnt, cnteq;
    __shared__ int   sidx[128];
    __shared__ float sw[128];
    if (t == 0) { cnt = 0; cnteq = 0; }
    __syncthreads();
    const float inv = 1.0f / (1.0f + (float)NND * EPS_ATTN);
    for (int i = t; i < NND; i += 1024) {
        float dv = dr[i];
        unsigned key = fkey(dv);
        bool take = false;
        if (key > pref) take = true;
        else if (key == pref) { int e = atomicAdd(&cnteq, 1); if (e < rem) take = true; }
        if (take) {
            int p = atomicAdd(&cnt, 1);
            if (p < 128) {
                sidx[p] = i;
                sw[p] = (expf(dv - M) / Z + EPS_ATTN) * inv;
            }
        }
    }
    __syncthreads();
    int nk = cnt < 128 ? cnt : 128;
    if (t < DD) {
        float acc = 0.0f;
        for (int sI = 0; sI < nk; sI++)
            acc = fmaf(sw[sI], g_qkv[(size_t)sidx[sI] * 768 + 512 + t], acc);
        g_e2cat[row * 2 * DD + DD + t] = acc;   // updates column block
    }
}

// ----- node-side: softmax(dots2), top-k_e -> H, fused residual x_out -------
__global__ void __launch_bounds__(256) node_final(const float* __restrict__ x,
                                                  float* __restrict__ out,
                                                  const int* __restrict__ ke_ptr) {
    int row = blockIdx.x, t = threadIdx.x;  // 256 threads
    const float* d2 = out + OFF_D2 + (size_t)row * NSS;
    float d0 = d2[t], d1 = d2[t + 256];
    __shared__ float red[256];
    red[t] = fmaxf(d0, d1); __syncthreads();
    for (int s = 128; s > 0; s >>= 1) { if (t < s) red[t] = fmaxf(red[t], red[t + s]); __syncthreads(); }
    float M = red[0]; __syncthreads();
    float e0 = expf(d0 - M), e1 = expf(d1 - M);
    red[t] = e0 + e1; __syncthreads();
    for (int s = 128; s > 0; s >>= 1) { if (t < s) red[t] += red[t + s]; __syncthreads(); }
    float Z = red[0]; __syncthreads();

    __shared__ float sv[512];
    __shared__ int fl[512];
    sv[t] = e0 / Z; sv[t + 256] = e1 / Z;
    fl[t] = 0; fl[t + 256] = 0;
    __syncthreads();

    int ke = *ke_ptr;
    __shared__ float rv[256]; __shared__ int ri[256];
    __shared__ int   selI[16]; __shared__ float selW[16];
    for (int it = 0; it < ke && it < 16; it++) {
        float bv = -1.0f; int bi = -1;
        if (!fl[t] && sv[t] > bv) { bv = sv[t]; bi = t; }
        if (!fl[t + 256] && sv[t + 256] > bv) { bv = sv[t + 256]; bi = t + 256; }
        rv[t] = bv; ri[t] = bi; __syncthreads();
        for (int st = 128; st > 0; st >>= 1) {
            if (t < st && rv[t + st] > rv[t]) { rv[t] = rv[t + st]; ri[t] = ri[t + st]; }
            __syncthreads();
        }
        if (t == 0) { selI[it] = ri[0]; selW[it] = rv[0]; fl[ri[0]] = 1; }
        __syncthreads();
    }
    out[OFF_H + (size_t)row * NSS + t]       = fl[t]       ? sv[t]       : 0.0f;
    out[OFF_H + (size_t)row * NSS + t + 256] = fl[t + 256] ? sv[t + 256] : 0.0f;
    float acc = x[(size_t)row * DD + t];
    for (int it = 0; it < ke && it < 16; it++)
        acc = fmaf(selW[it], g_eout[selI[it] * DD + t], acc);
    out[(size_t)row * DD + t] = acc;
}

// ------------------------- launch ----------------------------------------
extern "C" void kernel_launch(void* const* d_in, const int* in_sizes, int n_in,
                              void* d_out, int out_size) {
    const float* x    = (const float*)d_in[0];
    const float* noise= (const float*)d_in[1];
    const float* emu  = (const float*)d_in[2];
    const float* els  = (const float*)d_in[3];
    const float* lng  = (const float*)d_in[4];
    const float* lnb  = (const float*)d_in[5];
    const float* leg  = (const float*)d_in[6];
    const float* leb  = (const float*)d_in[7];
    const float* Wq = (const float*)d_in[8];  const float* bq = (const float*)d_in[9];
    const float* Wk = (const float*)d_in[10]; const float* bk = (const float*)d_in[11];
    const float* Wv = (const float*)d_in[12]; const float* bv = (const float*)d_in[13];
    const float* W1 = (const float*)d_in[14]; const float* b1 = (const float*)d_in[15];
    const float* W2 = (const float*)d_in[16]; const float* b2 = (const float*)d_in[17];
    const float* W  = (const float*)d_in[18]; const float* b  = (const float*)d_in[19];
    const int* knp  = (const int*)d_in[20];
    const int* kep  = (const int*)d_in[21];
    float* out = (float*)d_out;

    // scratch pointers (symbol lookups; no stream work, capture-safe)
    float *p_xin, *p_qkv, *p_dots, *p_qe, *p_k2, *p_eln, *p_e2, *p_h, *p_en, *p_wT, *p_bc;
    cudaGetSymbolAddress((void**)&p_xin, g_xin);
    cudaGetSymbolAddress((void**)&p_qkv, g_qkv);
    cudaGetSymbolAddress((void**)&p_dots, g_dots);
    cudaGetSymbolAddress((void**)&p_qe, g_qe);
    cudaGetSymbolAddress((void**)&p_k2, g_k2);
    cudaGetSymbolAddress((void**)&p_eln, g_eln);
    cudaGetSymbolAddress((void**)&p_e2, g_e2cat);
    cudaGetSymbolAddress((void**)&p_h, g_hmlp);
    cudaGetSymbolAddress((void**)&p_en, g_enew);
    cudaGetSymbolAddress((void**)&p_wT, g_wcatT);
    cudaGetSymbolAddress((void**)&p_bc, g_bcat);

    // 1) weight concat/transpose + biases
    prep_wcat<<<768, 256>>>(Wq, bq, Wk, bk, Wv, bv);
    // 2) node LN
    node_ln<<<NND, 256>>>(x, lng, lnb);
    // 3) edge sample + LN (also fills e2cat[:, :256])
    edge_prep<<<NSS, 256>>>(noise, emu, els, leg, leb);
    // 4) q_e = relu(e_ln @ Wq + bq)
    rowgemm<<<NSS, 256>>>(p_eln, DD, DD, Wq, bq, p_qe, DD, 1);
    // 5) qkv = xin @ WcatT^T + bcat, relu on cols >= 256 (kk, vv)
    {
        dim3 g(3 * DD / 128, NND / 128);
        sgemm_nt<<<g, 256>>>(p_xin, DD, p_wT, DD, p_qkv, 3 * DD, DD, p_bc, 1.0f, 256);
    }
    // 6) dots = (q_e @ kk^T) * D^-0.5
    {
        dim3 g(NND / 128, NSS / 128);
        sgemm_nt<<<g, 256>>>(p_qe, DD, p_qkv + 256, 3 * DD, p_dots, NND, DD,
                             nullptr, 0.0625f, 1 << 30);
    }
    // 7) per-edge softmax + exact top-k_n + weighted vv gather -> updates
    edge_select<<<NSS, 1024>>>(knp);
    // 8) edge MLP + heads
    rowgemm<<<NSS, 256>>>(p_e2, 2 * DD, 2 * DD, W1, b1, p_h, DD, 1);   // hidden
    rowgemm<<<NSS, 256>>>(p_h, DD, DD, W2, b2, p_en, DD, 0);           // e_new
    rowgemm<<<NSS, 256>>>(p_en, DD, DD, Wk, bk, p_k2, DD, 1);          // k2
    {
        float* p_eo; cudaGetSymbolAddress((void**)&p_eo, g_eout);
        rowgemm<<<NSS, 256>>>(p_en, DD, DD, W, b, p_eo, DD, 0);        // e_out
    }
    // 9) dots2 = (q2 @ k2^T) * D^-0.5 -> straight into output slab
    {
        dim3 g(NSS / 128, NND / 128);
        sgemm_nt<<<g, 256>>>(p_qkv, 3 * DD, p_k2, DD, out + OFF_D2, NSS, DD,
                             nullptr, 0.0625f, 1 << 30);
    }
    // 10) per-node softmax + top-k_e -> H, fused residual x_out
    node_final<<<NND, 256>>>(x, out, kep);
}

// round 10
// speedup vs baseline: 1.1626x; 1.1626x over previous
#include <cuda_runtime.h>
#include <math.h>
#include <stdint.h>

// Problem constants
#define NND   65536      // N nodes
#define DD    256        // feature dim
#define NSS   512        // edge slots
#define EPS_LN   1e-5f
#define EPS_ATTN 1e-8f

// Output layout: [x_out (N*D)] [H (N*NS)] [dots2 (N*NS)]
#define OFF_H   ((size_t)NND * DD)
#define OFF_D2  (OFF_H + (size_t)NND * NSS)

// ------------------------- device scratch (no allocations allowed) -------
__device__ float g_xin[(size_t)NND * DD];          // 64 MB  LN(x)
__device__ float g_qkv[(size_t)NND * 3 * DD];      // 192 MB [q2 | kk | vv] row stride 768
__device__ float g_dots[(size_t)NSS * NND];        // 128 MB edge->node logits
__device__ float g_eln[NSS * DD];
__device__ float g_qe[NSS * DD];
__device__ float g_e2cat[NSS * 2 * DD];            // [e_ln | updates]
__device__ float g_hmlp[NSS * DD];
__device__ float g_enew[NSS * DD];
__device__ float g_k2[NSS * DD];
__device__ float g_eout[NSS * DD];
__device__ float g_wcatT[3 * DD * DD];             // [768][256]: row j = column j of (Wq|Wk|Wv)
__device__ float g_bcat[3 * DD];

// ------------------------- small helpers ---------------------------------
__device__ __forceinline__ unsigned fkey(float f) {
    unsigned u = __float_as_uint(f);
    return (u & 0x80000000u) ? ~u : (u | 0x80000000u); // order-preserving map
}

// ------------------------- weight prep -----------------------------------
__global__ void prep_wcat(const float* __restrict__ Wq, const float* __restrict__ bq,
                          const float* __restrict__ Wk, const float* __restrict__ bk,
                          const float* __restrict__ Wv, const float* __restrict__ bv) {
    int idx = blockIdx.x * 256 + threadIdx.x;     // 768*256 total
    int j = idx >> 8, k = idx & 255;
    const float* W = (j < 256) ? Wq : ((j < 512) ? Wk : Wv);
    int jj = j & 255;
    g_wcatT[idx] = W[k * 256 + jj];
    if (k == 0) {
        const float* bb = (j < 256) ? bq : ((j < 512) ? bk : bv);
        g_bcat[j] = bb[jj];
    }
}

// ------------------------- row LayerNorm (nodes) --------------------------
__global__ void node_ln(const float* __restrict__ x, const float* __restrict__ g,
                        const float* __restrict__ b) {
    int row = blockIdx.x, t = threadIdx.x;   // 256 threads
    __shared__ float red[256];
    float v = x[(size_t)row * DD + t];
    red[t] = v; __syncthreads();
    for (int s = 128; s > 0; s >>= 1) { if (t < s) red[t] += red[t + s]; __syncthreads(); }
    float mean = red[0] * (1.0f / DD);
    __syncthreads();
    float d = v - mean;
    red[t] = d * d; __syncthreads();
    for (int s = 128; s > 0; s >>= 1) { if (t < s) red[t] += red[t + s]; __syncthreads(); }
    float var = red[0] * (1.0f / DD);
    g_xin[(size_t)row * DD + t] = d * rsqrtf(var + EPS_LN) * g[t] + b[t];
}

// ------------------------- edge prep: sample + LN -------------------------
__global__ void edge_prep(const float* __restrict__ noise, const float* __restrict__ mu,
                          const float* __restrict__ ls, const float* __restrict__ g,
                          const float* __restrict__ b) {
    int row = blockIdx.x, t = threadIdx.x;   // 512 blocks x 256 threads
    __shared__ float red[256];
    float v = mu[t] + expf(ls[t]) * noise[row * DD + t];
    red[t] = v; __syncthreads();
    for (int s = 128; s > 0; s >>= 1) { if (t < s) red[t] += red[t + s]; __syncthreads(); }
    float mean = red[0] * (1.0f / DD);
    __syncthreads();
    float d = v - mean;
    red[t] = d * d; __syncthreads();
    for (int s = 128; s > 0; s >>= 1) { if (t < s) red[t] += red[t + s]; __syncthreads(); }
    float var = red[0] * (1.0f / DD);
    float o = d * rsqrtf(var + EPS_LN) * g[t] + b[t];
    g_eln[row * DD + t] = o;
    g_e2cat[row * 2 * DD + t] = o;
}

// ------------- small dense: one row per block, 256 output cols ------------
__global__ void rowgemm(const float* __restrict__ X, int ldx, int K,
                        const float* __restrict__ Wm, const float* __restrict__ bias,
                        float* __restrict__ Y, int ldy, int relu) {
    __shared__ float xr[512];
    int row = blockIdx.x, t = threadIdx.x;
    for (int i = t; i < K; i += 256) xr[i] = X[(size_t)row * ldx + i];
    __syncthreads();
    float acc = bias[t];
    for (int k = 0; k < K; k++) acc = fmaf(xr[k], Wm[k * 256 + t], acc);
    if (relu) acc = fmaxf(acc, 0.0f);
    Y[(size_t)row * ldy + t] = acc;
}

// ------------------------- big SGEMM: C = scale*A*B^T (+bias, relu) -------
// A[M,K] lda, B[N,K] ldb (K-contiguous), C[M,N] ldc. K % 16 == 0,
// M,N % 128 == 0. 128x128x16 tile, double-buffered, 256 threads, 8x8 micro
// (split 4+4 rows/cols for conflict-free float4 LDS). fp32 FFMA, sequential
// k-order accumulation (bitwise-stable numerics).
__global__ void __launch_bounds__(256, 2) sgemm_nt(
        const float* __restrict__ A, int lda,
        const float* __restrict__ B, int ldb,
        float* __restrict__ C, int ldc, int K,
        const float* __restrict__ bias, float scale, int relu_from) {
    __shared__ float As[2][16][132];
    __shared__ float Bs[2][16][132];
    const int tid = threadIdx.x;
    const int bm = blockIdx.y * 128, bn = blockIdx.x * 128;
    const int tx = tid & 15, ty = tid >> 4;

    // loader mapping: row = tid&127 (conflict-free STS), k-half = tid>>7
    const int lr = tid & 127;
    const int lk = (tid >> 7) * 8;
    const float* Ag = A + (size_t)(bm + lr) * lda + lk;
    const float* Bg = B + (size_t)(bn + lr) * ldb + lk;

    float acc[8][8] = {};

    // prologue: load chunk 0 into buffer 0
    float4 a0 = *(const float4*)(Ag);
    float4 a1 = *(const float4*)(Ag + 4);
    float4 b0 = *(const float4*)(Bg);
    float4 b1 = *(const float4*)(Bg + 4);
    As[0][lk + 0][lr] = a0.x; As[0][lk + 1][lr] = a0.y;
    As[0][lk + 2][lr] = a0.z; As[0][lk + 3][lr] = a0.w;
    As[0][lk + 4][lr] = a1.x; As[0][lk + 5][lr] = a1.y;
    As[0][lk + 6][lr] = a1.z; As[0][lk + 7][lr] = a1.w;
    Bs[0][lk + 0][lr] = b0.x; Bs[0][lk + 1][lr] = b0.y;
    Bs[0][lk + 2][lr] = b0.z; Bs[0][lk + 3][lr] = b0.w;
    Bs[0][lk + 4][lr] = b1.x; Bs[0][lk + 5][lr] = b1.y;
    Bs[0][lk + 6][lr] = b1.z; Bs[0][lk + 7][lr] = b1.w;
    __syncthreads();

    const int nIter = K >> 4;
    for (int it = 0; it < nIter; it++) {
        const int cur = it & 1;
        if (it + 1 < nIter) {
            int k0 = (it + 1) << 4;
            a0 = *(const float4*)(Ag + k0);
            a1 = *(const float4*)(Ag + k0 + 4);
            b0 = *(const float4*)(Bg + k0);
            b1 = *(const float4*)(Bg + k0 + 4);
        }
#pragma unroll
        for (int kk = 0; kk < 16; kk++) {
            float a[8], b[8];
            *(float4*)(a)     = *(const float4*)&As[cur][kk][ty * 4];
            *(float4*)(a + 4) = *(const float4*)&As[cur][kk][64 + ty * 4];
            *(float4*)(b)     = *(const float4*)&Bs[cur][kk][tx * 4];
            *(float4*)(b + 4) = *(const float4*)&Bs[cur][kk][64 + tx * 4];
#pragma unroll
            for (int i = 0; i < 8; i++)
#pragma unroll
                for (int j = 0; j < 8; j++)
                    acc[i][j] = fmaf(a[i], b[j], acc[i][j]);
        }
        if (it + 1 < nIter) {
            const int nxt = cur ^ 1;
            As[nxt][lk + 0][lr] = a0.x; As[nxt][lk + 1][lr] = a0.y;
            As[nxt][lk + 2][lr] = a0.z; As[nxt][lk + 3][lr] = a0.w;
            As[nxt][lk + 4][lr] = a1.x; As[nxt][lk + 5][lr] = a1.y;
            As[nxt][lk + 6][lr] = a1.z; As[nxt][lk + 7][lr] = a1.w;
            Bs[nxt][lk + 0][lr] = b0.x; Bs[nxt][lk + 1][lr] = b0.y;
            Bs[nxt][lk + 2][lr] = b0.z; Bs[nxt][lk + 3][lr] = b0.w;
            Bs[nxt][lk + 4][lr] = b1.x; Bs[nxt][lk + 5][lr] = b1.y;
            Bs[nxt][lk + 6][lr] = b1.z; Bs[nxt][lk + 7][lr] = b1.w;
            __syncthreads();
        }
    }

    // epilogue: rows {ty*4+i, 64+ty*4+i}, cols {tx*4+j, 64+tx*4+j}
#pragma unroll
    for (int ih = 0; ih < 2; ih++) {
#pragma unroll
        for (int i = 0; i < 4; i++) {
            int row = bm + ih * 64 + ty * 4 + i;
#pragma unroll
            for (int jh = 0; jh < 2; jh++) {
                int col = bn + jh * 64 + tx * 4;
                float4 v;
                float* vp = (float*)&v;
#pragma unroll
                for (int j = 0; j < 4; j++) {
                    float t = acc[ih * 4 + i][jh * 4 + j] * scale;
                    if (bias) t += bias[col + j];
                    if (col + j >= relu_from) t = fmaxf(t, 0.0f);
                    vp[j] = t;
                }
                *(float4*)&C[(size_t)row * ldc + col] = v;
            }
        }
    }
}

// ----- edge-side: softmax stats + exact top-k_n select + weighted gather ---
// Pass structure (4 sweeps of the row): fused(max/sum + hist0), hist1, hist2,
// select.
__global__ void __launch_bounds__(1024) edge_select(const int* __restrict__ kn_ptr) {
    const int row = blockIdx.x;
    const int t = threadIdx.x;                    // 1024 threads
    const float* dr = g_dots + (size_t)row * NND;
    __shared__ float red[1024];
    __shared__ unsigned hist[2048];
    __shared__ unsigned sb_bin;
    __shared__ int sb_rem;

    // pass 0 (fused): online max / sum-exp  +  histogram of bits [31:21)
    for (int i = t; i < 2048; i += 1024) hist[i] = 0;
    __syncthreads();
    float m = -3.0e38f, s = 0.0f;
    for (int i = t; i < NND; i += 1024) {
        float dv = dr[i];
        if (dv > m) { s = s * expf(m - dv) + 1.0f; m = dv; }
        else        { s += expf(dv - m); }
        atomicAdd(&hist[fkey(dv) >> 21], 1u);
    }
    red[t] = m; __syncthreads();
    for (int st = 512; st > 0; st >>= 1) { if (t < st) red[t] = fmaxf(red[t], red[t + st]); __syncthreads(); }
    float M = red[0]; __syncthreads();
    red[t] = s * expf(m - M); __syncthreads();
    for (int st = 512; st > 0; st >>= 1) { if (t < st) red[t] += red[t + st]; __syncthreads(); }
    float Z = red[0]; __syncthreads();

    int kq = *kn_ptr;
    unsigned pref = 0, pmask = 0;
    int rem = kq;
    // resolve pass-0 histogram
    if (t == 0) {
        int cum = 0, b = 2047;
        for (; b >= 0; b--) { cum += (int)hist[b]; if (cum >= rem) break; }
        if (b < 0) b = 0;
        sb_bin = (unsigned)b;
        sb_rem = rem - (cum - (int)hist[b]);
    }
    __syncthreads();
    pref = sb_bin << 21;
    pmask = 2047u << 21;
    rem = sb_rem;
    __syncthreads();

    // refinement passes: bits [21:10) then [10:0)
    const int shifts[2] = {10, 0};
    const int bcnts[2]  = {2048, 1024};
    for (int p = 0; p < 2; p++) {
        int bc = bcnts[p], sh = shifts[p];
        for (int i = t; i < bc; i += 1024) hist[i] = 0;
        __syncthreads();
        for (int i = t; i < NND; i += 1024) {
            unsigned key = fkey(dr[i]);
            if ((key & pmask) == pref) atomicAdd(&hist[(key >> sh) & (bc - 1)], 1u);
        }
        __syncthreads();
        if (t == 0) {
            int cum = 0, b = bc - 1;
            for (; b >= 0; b--) { cum += (int)hist[b]; if (cum >= rem) break; }
            if (b < 0) b = 0;
            sb_bin = (unsigned)b;
            sb_rem = rem - (cum - (int)hist[b]);
        }
        __syncthreads();
        pref |= sb_bin << sh;
        pmask |= (unsigned)(bc - 1) << sh;
        rem = sb_rem;
        __syncthreads();
    }

    // threshold key == pref; take all keys > pref, plus `rem` keys == pref
    __shared__ int cnt, cnteq;
    __shared__ int   sidx[128];
    __shared__ float sw[128];
    if (t == 0) { cnt = 0; cnteq = 0; }
    __syncthreads();
    const float inv = 1.0f / (1.0f + (float)NND * EPS_ATTN);
    for (int i = t; i < NND; i += 1024) {
        float dv = dr[i];
        unsigned key = fkey(dv);
        bool take = false;
        if (key > pref) take = true;
        else if (key == pref) { int e = atomicAdd(&cnteq, 1); if (e < rem) take = true; }
        if (take) {
            int p = atomicAdd(&cnt, 1);
            if (p < 128) {
                sidx[p] = i;
                sw[p] = (expf(dv - M) / Z + EPS_ATTN) * inv;
            }
        }
    }
    __syncthreads();
    int nk = cnt < 128 ? cnt : 128;
    if (t < DD) {
        float acc = 0.0f;
        for (int sI = 0; sI < nk; sI++)
            acc = fmaf(sw[sI], g_qkv[(size_t)sidx[sI] * 768 + 512 + t], acc);
        g_e2cat[row * 2 * DD + DD + t] = acc;   // updates column block
    }
}

// ----- node-side: softmax(dots2), top-k_e -> H, fused residual x_out -------
__global__ void __launch_bounds__(256) node_final(const float* __restrict__ x,
                                                  float* __restrict__ out,
                                                  const int* __restrict__ ke_ptr) {
    int row = blockIdx.x, t = threadIdx.x;  // 256 threads
    const float* d2 = out + OFF_D2 + (size_t)row * NSS;
    float d0 = d2[t], d1 = d2[t + 256];
    __shared__ float red[256];
    red[t] = fmaxf(d0, d1); __syncthreads();
    for (int s = 128; s > 0; s >>= 1) { if (t < s) red[t] = fmaxf(red[t], red[t + s]); __syncthreads(); }
    float M = red[0]; __syncthreads();
    float e0 = expf(d0 - M), e1 = expf(d1 - M);
    red[t] = e0 + e1; __syncthreads();
    for (int s = 128; s > 0; s >>= 1) { if (t < s) red[t] += red[t + s]; __syncthreads(); }
    float Z = red[0]; __syncthreads();

    __shared__ float sv[512];
    __shared__ int fl[512];
    sv[t] = e0 / Z; sv[t + 256] = e1 / Z;
    fl[t] = 0; fl[t + 256] = 0;
    __syncthreads();

    int ke = *ke_ptr;
    __shared__ float rv[256]; __shared__ int ri[256];
    __shared__ int   selI[16]; __shared__ float selW[16];
    for (int it = 0; it < ke && it < 16; it++) {
        float bv = -1.0f; int bi = -1;
        if (!fl[t] && sv[t] > bv) { bv = sv[t]; bi = t; }
        if (!fl[t + 256] && sv[t + 256] > bv) { bv = sv[t + 256]; bi = t + 256; }
        rv[t] = bv; ri[t] = bi; __syncthreads();
        for (int st = 128; st > 0; st >>= 1) {
            if (t < st && rv[t + st] > rv[t]) { rv[t] = rv[t + st]; ri[t] = ri[t + st]; }
            __syncthreads();
        }
        if (t == 0) { selI[it] = ri[0]; selW[it] = rv[0]; fl[ri[0]] = 1; }
        __syncthreads();
    }
    out[OFF_H + (size_t)row * NSS + t]       = fl[t]       ? sv[t]       : 0.0f;
    out[OFF_H + (size_t)row * NSS + t + 256] = fl[t + 256] ? sv[t + 256] : 0.0f;
    float acc = x[(size_t)row * DD + t];
    for (int it = 0; it < ke && it < 16; it++)
        acc = fmaf(selW[it], g_eout[selI[it] * DD + t], acc);
    out[(size_t)row * DD + t] = acc;
}

// ------------------------- launch ----------------------------------------
extern "C" void kernel_launch(void* const* d_in, const int* in_sizes, int n_in,
                              void* d_out, int out_size) {
    const float* x    = (const float*)d_in[0];
    const float* noise= (const float*)d_in[1];
    const float* emu  = (const float*)d_in[2];
    const float* els  = (const float*)d_in[3];
    const float* lng  = (const float*)d_in[4];
    const float* lnb  = (const float*)d_in[5];
    const float* leg  = (const float*)d_in[6];
    const float* leb  = (const float*)d_in[7];
    const float* Wq = (const float*)d_in[8];  const float* bq = (const float*)d_in[9];
    const float* Wk = (const float*)d_in[10]; const float* bk = (const float*)d_in[11];
    const float* Wv = (const float*)d_in[12]; const float* bv = (const float*)d_in[13];
    const float* W1 = (const float*)d_in[14]; const float* b1 = (const float*)d_in[15];
    const float* W2 = (const float*)d_in[16]; const float* b2 = (const float*)d_in[17];
    const float* W  = (const float*)d_in[18]; const float* b  = (const float*)d_in[19];
    const int* knp  = (const int*)d_in[20];
    const int* kep  = (const int*)d_in[21];
    float* out = (float*)d_out;

    // scratch pointers (symbol lookups; no stream work, capture-safe)
    float *p_xin, *p_qkv, *p_dots, *p_qe, *p_k2, *p_eln, *p_e2, *p_h, *p_en, *p_wT, *p_bc, *p_eo;
    cudaGetSymbolAddress((void**)&p_xin, g_xin);
    cudaGetSymbolAddress((void**)&p_qkv, g_qkv);
    cudaGetSymbolAddress((void**)&p_dots, g_dots);
    cudaGetSymbolAddress((void**)&p_qe, g_qe);
    cudaGetSymbolAddress((void**)&p_k2, g_k2);
    cudaGetSymbolAddress((void**)&p_eln, g_eln);
    cudaGetSymbolAddress((void**)&p_e2, g_e2cat);
    cudaGetSymbolAddress((void**)&p_h, g_hmlp);
    cudaGetSymbolAddress((void**)&p_en, g_enew);
    cudaGetSymbolAddress((void**)&p_wT, g_wcatT);
    cudaGetSymbolAddress((void**)&p_bc, g_bcat);
    cudaGetSymbolAddress((void**)&p_eo, g_eout);

    // 1) weight concat/transpose + biases
    prep_wcat<<<768, 256>>>(Wq, bq, Wk, bk, Wv, bv);
    // 2) node LN
    node_ln<<<NND, 256>>>(x, lng, lnb);
    // 3) edge sample + LN (also fills e2cat[:, :256])
    edge_prep<<<NSS, 256>>>(noise, emu, els, leg, leb);
    // 4) q_e = relu(e_ln @ Wq + bq)
    rowgemm<<<NSS, 256>>>(p_eln, DD, DD, Wq, bq, p_qe, DD, 1);
    // 5) qkv = xin @ WcatT^T + bcat, relu on cols >= 256 (kk, vv)
    {
        dim3 g(3 * DD / 128, NND / 128);
        sgemm_nt<<<g, 256>>>(p_xin, DD, p_wT, DD, p_qkv, 3 * DD, DD, p_bc, 1.0f, 256);
    }
    // 6) dots = (q_e @ kk^T) * D^-0.5
    {
        dim3 g(NND / 128, NSS / 128);
        sgemm_nt<<<g, 256>>>(p_qe, DD, p_qkv + 256, 3 * DD, p_dots, NND, DD,
                             nullptr, 0.0625f, 1 << 30);
    }
    // 7) per-edge softmax + exact top-k_n + weighted vv gather -> updates
    edge_select<<<NSS, 1024>>>(knp);
    // 8) edge MLP + heads
    rowgemm<<<NSS, 256>>>(p_e2, 2 * DD, 2 * DD, W1, b1, p_h, DD, 1);   // hidden
    rowgemm<<<NSS, 256>>>(p_h, DD, DD, W2, b2, p_en, DD, 0);           // e_new
    rowgemm<<<NSS, 256>>>(p_en, DD, DD, Wk, bk, p_k2, DD, 1);          // k2
    rowgemm<<<NSS, 256>>>(p_en, DD, DD, W, b, p_eo, DD, 0);            // e_out
    // 9) dots2 = (q2 @ k2^T) * D^-0.5 -> straight into output slab
    {
        dim3 g(NSS / 128, NND / 128);
        sgemm_nt<<<g, 256>>>(p_qkv, 3 * DD, p_k2, DD, out + OFF_D2, NSS, DD,
                             nullptr, 0.0625f, 1 << 30);
    }
    // 10) per-node softmax + top-k_e -> H, fused residual x_out
    node_final<<<NND, 256>>>(x, out, kep);
}